// round 2
// baseline (speedup 1.0000x reference)
#include <cuda_runtime.h>
#include <cstdint>

#define T_  256
#define B_  128
#define I_  512
#define H_  1024
#define L_  4
#define G3H 3072
#define TB  (T_ * B_)

// scan tiling
#define RT 64            // batch rows per CTA
#define CT 16            // cols per gate per CTA (48 W rows total)
#define WS_STRIDE 1028   // padded k-stride for W smem (conflict-free)
#define AS_STRIDE 68     // padded k-stride for h smem chunk
#define SCAN_SMEM_WORDS (48 * WS_STRIDE + 64 * AS_STRIDE)
#define SCAN_SMEM_BYTES (SCAN_SMEM_WORDS * 4)

// Scratch (static device allocations are the sanctioned workaround)
__device__ float g_gi[(size_t)TB * G3H];   // per-layer input projections
__device__ float g_ys[(size_t)TB * H_];    // inter-layer activations
__device__ float g_h[2][B_ * H_];          // ping-pong hidden state
__device__ unsigned g_bar;                 // grid barrier counter

__device__ __forceinline__ uint32_t f2tf(float x) {
    uint32_t r;
    asm("cvt.rna.tf32.f32 %0, %1;\n" : "=r"(r) : "f"(x));
    return r;
}

__device__ __forceinline__ void mma8(float* c, const uint32_t* a, const uint32_t* b) {
    asm volatile(
        "mma.sync.aligned.m16n8k8.row.col.f32.tf32.tf32.f32 "
        "{%0,%1,%2,%3}, {%4,%5,%6,%7}, {%8,%9}, {%0,%1,%2,%3};\n"
        : "+f"(c[0]), "+f"(c[1]), "+f"(c[2]), "+f"(c[3])
        : "r"(a[0]), "r"(a[1]), "r"(a[2]), "r"(a[3]), "r"(b[0]), "r"(b[1]));
}

// ---------------------------------------------------------------------------
// gi = A @ W^T + bias      A: (TB, K) row-major, W: (3H, K) row-major
// CTA tile 128x64, BK=32, 256 threads (warp grid 4m x 2n, warp tile 32x32)
// ---------------------------------------------------------------------------
__global__ __launch_bounds__(256) void gi_gemm(
    const float* __restrict__ A_ext,   // x for layer 0, else null (use g_ys)
    const float* __restrict__ W,
    const float* __restrict__ bias,
    int K)
{
    __shared__ uint32_t As[128][36];
    __shared__ uint32_t Bs[64][36];

    const float* A = A_ext ? A_ext : g_ys;

    int n0 = blockIdx.x * 64;
    int m0 = blockIdx.y * 128;
    int tid = threadIdx.x;
    int warp = tid >> 5, lane = tid & 31;
    int g4 = lane >> 2, tig = lane & 3;
    int wm = warp & 3, wn = warp >> 2;
    int mb = wm * 32, nb = wn * 32;

    float acc[2][4][4];
    #pragma unroll
    for (int i = 0; i < 2; i++)
        #pragma unroll
        for (int j = 0; j < 4; j++)
            #pragma unroll
            for (int k = 0; k < 4; k++) acc[i][j][k] = 0.f;

    int arow = tid >> 3;            // 0..31
    int acol = (tid & 7) * 4;       // 0,4,...,28

    for (int k0 = 0; k0 < K; k0 += 32) {
        #pragma unroll
        for (int r = 0; r < 4; r++) {
            int row = arow + r * 32;
            float4 v = *reinterpret_cast<const float4*>(A + (size_t)(m0 + row) * K + k0 + acol);
            As[row][acol]     = f2tf(v.x);
            As[row][acol + 1] = f2tf(v.y);
            As[row][acol + 2] = f2tf(v.z);
            As[row][acol + 3] = f2tf(v.w);
        }
        #pragma unroll
        for (int r = 0; r < 2; r++) {
            int row = arow + r * 32;
            float4 v = *reinterpret_cast<const float4*>(W + (size_t)(n0 + row) * K + k0 + acol);
            Bs[row][acol]     = f2tf(v.x);
            Bs[row][acol + 1] = f2tf(v.y);
            Bs[row][acol + 2] = f2tf(v.z);
            Bs[row][acol + 3] = f2tf(v.w);
        }
        __syncthreads();

        #pragma unroll
        for (int kk = 0; kk < 32; kk += 8) {
            uint32_t af[2][4], bf[4][2];
            #pragma unroll
            for (int mf = 0; mf < 2; mf++) {
                int r0 = mb + mf * 16 + g4;
                af[mf][0] = As[r0][kk + tig];
                af[mf][1] = As[r0 + 8][kk + tig];
                af[mf][2] = As[r0][kk + tig + 4];
                af[mf][3] = As[r0 + 8][kk + tig + 4];
            }
            #pragma unroll
            for (int nf = 0; nf < 4; nf++) {
                int c0 = nb + nf * 8 + g4;
                bf[nf][0] = Bs[c0][kk + tig];
                bf[nf][1] = Bs[c0][kk + tig + 4];
            }
            #pragma unroll
            for (int mf = 0; mf < 2; mf++)
                #pragma unroll
                for (int nf = 0; nf < 4; nf++)
                    mma8(acc[mf][nf], af[mf], bf[nf]);
        }
        __syncthreads();
    }

    #pragma unroll
    for (int mf = 0; mf < 2; mf++) {
        #pragma unroll
        for (int nf = 0; nf < 4; nf++) {
            int col = n0 + nb + nf * 8 + tig * 2;
            float b0 = bias[col], b1 = bias[col + 1];
            int r0 = m0 + mb + mf * 16 + g4;
            g_gi[(size_t)r0 * G3H + col]           = acc[mf][nf][0] + b0;
            g_gi[(size_t)r0 * G3H + col + 1]       = acc[mf][nf][1] + b1;
            g_gi[(size_t)(r0 + 8) * G3H + col]     = acc[mf][nf][2] + b0;
            g_gi[(size_t)(r0 + 8) * G3H + col + 1] = acc[mf][nf][3] + b1;
        }
    }
}

// ---------------------------------------------------------------------------
// Persistent scan: all 256 GRU timesteps of one layer in ONE kernel.
// Grid = 128 CTAs (2 batch tiles x 64 col groups), 256 threads (8 warps:
// 4 row-groups of 16 x 2 col-groups of 8-per-gate). The CTA's 48-row W slice
// (3 gates x 16 cols) lives in smem as TF32 for the whole layer. A grid
// barrier (monotonic atomic counter, all CTAs resident) separates steps.
// ---------------------------------------------------------------------------
__global__ __launch_bounds__(256, 1) void gru_scan(
    const float* __restrict__ Whh,     // (3H, H) this layer
    const float* __restrict__ bhh,     // (3H)
    const int*   __restrict__ lens,
    float* __restrict__ y_last,        // d_out ys base if last layer, else null
    float* __restrict__ h_final)       // d_out h slice for this layer
{
    extern __shared__ uint32_t sm[];
    uint32_t* Ws = sm;                       // 48 x WS_STRIDE
    uint32_t* As = sm + 48 * WS_STRIDE;      // 64 x AS_STRIDE

    int cta = blockIdx.x;
    int bt = cta & 1;            // batch tile 0/1
    int cg = cta >> 1;           // col group 0..63
    int tid = threadIdx.x;
    int warp = tid >> 5, lane = tid & 31;
    int g4 = lane >> 2, tig = lane & 3;
    int wrow = warp & 3, wcol = warp >> 2;

    // Load W slice into smem once (TF32): rows r=q*16+rl -> global q*H + cg*16+rl
    for (int i = tid; i < 48 * 256; i += 256) {
        int r = i >> 8;              // 0..47
        int c = (i & 255) << 2;      // 0..1020
        int q = r >> 4, rl = r & 15;
        float4 v = *reinterpret_cast<const float4*>(
            Whh + (size_t)(q * H_ + cg * CT + rl) * H_ + c);
        uint32_t* dst = Ws + r * WS_STRIDE + c;
        dst[0] = f2tf(v.x); dst[1] = f2tf(v.y); dst[2] = f2tf(v.z); dst[3] = f2tf(v.w);
    }

    // Per-thread constants
    int m0 = bt * RT + wrow * 16 + g4;          // rows m0, m0+8
    int jbase = cg * CT + wcol * 8 + tig * 2;   // per-gate col pair base
    float bj[3][2];
    #pragma unroll
    for (int q = 0; q < 3; q++) {
        bj[q][0] = bhh[q * H_ + jbase];
        bj[q][1] = bhh[q * H_ + jbase + 1];
    }
    int len0 = lens[m0];
    int len1 = lens[m0 + 8];
    __syncthreads();

    for (int t = 0; t < T_; t++) {
        const float* hin = g_h[t & 1];
        float* hout = g_h[(t & 1) ^ 1];

        float acc[3][4];
        #pragma unroll
        for (int q = 0; q < 3; q++)
            #pragma unroll
            for (int i = 0; i < 4; i++) acc[q][i] = 0.f;

        for (int k0 = 0; k0 < H_; k0 += 64) {
            // stage 64 rows x 64 k of h (TF32)
            #pragma unroll
            for (int it = 0; it < 4; it++) {
                int i = tid + it * 256;
                int row = i >> 4;
                int col = (i & 15) << 2;
                float4 v = *reinterpret_cast<const float4*>(
                    hin + (size_t)(bt * RT + row) * H_ + k0 + col);
                uint32_t* dst = As + row * AS_STRIDE + col;
                dst[0] = f2tf(v.x); dst[1] = f2tf(v.y);
                dst[2] = f2tf(v.z); dst[3] = f2tf(v.w);
            }
            __syncthreads();

            #pragma unroll
            for (int kk = 0; kk < 64; kk += 8) {
                uint32_t af[4];
                int r0 = (wrow * 16 + g4) * AS_STRIDE;
                af[0] = As[r0 + kk + tig];
                af[1] = As[r0 + 8 * AS_STRIDE + kk + tig];
                af[2] = As[r0 + kk + tig + 4];
                af[3] = As[r0 + 8 * AS_STRIDE + kk + tig + 4];
                #pragma unroll
                for (int q = 0; q < 3; q++) {
                    uint32_t bf[2];
                    int wr = (q * 16 + wcol * 8 + g4) * WS_STRIDE + k0 + kk;
                    bf[0] = Ws[wr + tig];
                    bf[1] = Ws[wr + tig + 4];
                    mma8(acc[q], af, bf);
                }
            }
            __syncthreads();
        }

        // Fused gate epilogue
        const float* gi_t = g_gi + (size_t)t * B_ * G3H;
        float* yrow = y_last ? (y_last + (size_t)t * B_ * H_)
                             : (g_ys + (size_t)t * B_ * H_);
        #pragma unroll
        for (int ri = 0; ri < 2; ri++) {
            int m = m0 + ri * 8;
            bool msk = t < (ri ? len1 : len0);
            const float* gi = gi_t + (size_t)m * G3H;
            #pragma unroll
            for (int ci = 0; ci < 2; ci++) {
                int j = jbase + ci;
                int ai = ri * 2 + ci;
                float ghr = acc[0][ai] + bj[0][ci];
                float ghz = acc[1][ai] + bj[1][ci];
                float ghn = acc[2][ai] + bj[2][ci];
                float rg = 1.f / (1.f + __expf(-(gi[j] + ghr)));
                float zg = 1.f / (1.f + __expf(-(gi[H_ + j] + ghz)));
                float ng = tanhf(gi[2 * H_ + j] + rg * ghn);
                float hold = hin[(size_t)m * H_ + j];
                float hnew = (1.f - zg) * ng + zg * hold;
                float hv = msk ? hnew : hold;
                hout[(size_t)m * H_ + j] = hv;
                yrow[(size_t)m * H_ + j] = msk ? hnew : 0.f;
                if (t == T_ - 1) h_final[(size_t)m * H_ + j] = hv;
            }
        }

        // Grid barrier (all CTAs resident: 128 CTAs, 1/SM by smem)
        __syncthreads();
        if (tid == 0) {
            __threadfence();
            atomicAdd(&g_bar, 1u);
            unsigned target = (unsigned)gridDim.x * (unsigned)(t + 1);
            unsigned v;
            do {
                asm volatile("ld.global.acquire.gpu.u32 %0, [%1];"
                             : "=r"(v) : "l"(&g_bar) : "memory");
            } while (v < target);
        }
        __syncthreads();
    }
}

__global__ void init_h(const float* __restrict__ hsrc) {
    int i = blockIdx.x * blockDim.x + threadIdx.x;
    if (i < B_ * H_) g_h[0][i] = hsrc[i];
    if (i == 0) g_bar = 0u;
}

extern "C" void kernel_launch(void* const* d_in, const int* in_sizes, int n_in,
                              void* d_out, int out_size) {
    const float* x          = (const float*)d_in[0];
    const float* hidden     = (const float*)d_in[1];
    const float* w_ih0      = (const float*)d_in[2];
    const float* w_ih_rest  = (const float*)d_in[3];
    const float* w_hh       = (const float*)d_in[4];
    const float* b_ih       = (const float*)d_in[5];
    const float* b_hh       = (const float*)d_in[6];
    const int*   lens       = (const int*)d_in[n_in - 1];  // input_lengths is last

    float* out_ys = (float*)d_out;                       // (T, B, H)
    float* out_h  = out_ys + (size_t)T_ * B_ * H_;       // (L, B, H)

    cudaFuncSetAttribute(gru_scan, cudaFuncAttributeMaxDynamicSharedMemorySize,
                         SCAN_SMEM_BYTES);

    for (int l = 0; l < L_; l++) {
        int K = (l == 0) ? I_ : H_;
        const float* wih = (l == 0) ? w_ih0 : (w_ih_rest + (size_t)(l - 1) * G3H * H_);
        dim3 grid(G3H / 64, TB / 128);
        gi_gemm<<<grid, 256>>>((l == 0) ? x : nullptr, wih, b_ih + (size_t)l * G3H, K);

        init_h<<<(B_ * H_ + 255) / 256, 256>>>(hidden + (size_t)l * B_ * H_);

        gru_scan<<<128, 256, SCAN_SMEM_BYTES>>>(
            w_hh + (size_t)l * G3H * H_,
            b_hh + (size_t)l * G3H,
            lens,
            (l == L_ - 1) ? out_ys : nullptr,
            out_h + (size_t)l * B_ * H_);
    }
}

// round 3
// speedup vs baseline: 1.4519x; 1.4519x over previous
#include <cuda_runtime.h>
#include <cstdint>

#define T_  256
#define B_  128
#define I_  512
#define H_  1024
#define L_  4
#define G3H 3072
#define TB  (T_ * B_)

// scan tiling
#define RT 64            // batch rows per CTA
#define CT 16            // cols per gate per CTA (48 W rows total)
#define WS_STRIDE 1028   // padded k-stride for W smem (conflict-free)
#define AS_STRIDE 68     // padded k-stride for h smem chunk
#define BUF_WORDS (64 * AS_STRIDE)
#define SCAN_SMEM_WORDS (48 * WS_STRIDE + 2 * BUF_WORDS)
#define SCAN_SMEM_BYTES (SCAN_SMEM_WORDS * 4)   // 232,192 <= 232,448 limit

// Scratch (static device allocations are the sanctioned workaround)
__device__ float    g_gi[(size_t)TB * G3H];   // per-layer input projections
__device__ float    g_ys[(size_t)TB * H_];    // inter-layer activations
__device__ uint32_t g_htf[2][B_ * H_];        // ping-pong hidden state, TF32 bits
__device__ unsigned g_bar;                    // grid barrier counter
__device__ unsigned g_ack;                    // end-of-scan reset ack

__device__ __forceinline__ uint32_t f2tf(float x) {
    uint32_t r;
    asm("cvt.rna.tf32.f32 %0, %1;\n" : "=r"(r) : "f"(x));
    return r;
}

__device__ __forceinline__ void mma8(float* c, const uint32_t* a, const uint32_t* b) {
    asm volatile(
        "mma.sync.aligned.m16n8k8.row.col.f32.tf32.tf32.f32 "
        "{%0,%1,%2,%3}, {%4,%5,%6,%7}, {%8,%9}, {%0,%1,%2,%3};\n"
        : "+f"(c[0]), "+f"(c[1]), "+f"(c[2]), "+f"(c[3])
        : "r"(a[0]), "r"(a[1]), "r"(a[2]), "r"(a[3]), "r"(b[0]), "r"(b[1]));
}

__device__ __forceinline__ void cp16(uint32_t dst_smem, const void* src) {
    asm volatile("cp.async.ca.shared.global [%0], [%1], 16;\n"
                 :: "r"(dst_smem), "l"(src));
}

// ---------------------------------------------------------------------------
// gi = A @ W^T + bias      A: (TB, K) row-major, W: (3H, K) row-major
// CTA tile 128x64, BK=32, 256 threads (warp grid 4m x 2n, warp tile 32x32)
// ---------------------------------------------------------------------------
__global__ __launch_bounds__(256) void gi_gemm(
    const float* __restrict__ A_ext,   // x for layer 0, else null (use g_ys)
    const float* __restrict__ W,
    const float* __restrict__ bias,
    int K)
{
    __shared__ uint32_t As[128][36];
    __shared__ uint32_t Bs[64][36];

    const float* A = A_ext ? A_ext : g_ys;

    int n0 = blockIdx.x * 64;
    int m0 = blockIdx.y * 128;
    int tid = threadIdx.x;
    int warp = tid >> 5, lane = tid & 31;
    int g4 = lane >> 2, tig = lane & 3;
    int wm = warp & 3, wn = warp >> 2;
    int mb = wm * 32, nb = wn * 32;

    float acc[2][4][4];
    #pragma unroll
    for (int i = 0; i < 2; i++)
        #pragma unroll
        for (int j = 0; j < 4; j++)
            #pragma unroll
            for (int k = 0; k < 4; k++) acc[i][j][k] = 0.f;

    int arow = tid >> 3;            // 0..31
    int acol = (tid & 7) * 4;       // 0,4,...,28

    for (int k0 = 0; k0 < K; k0 += 32) {
        #pragma unroll
        for (int r = 0; r < 4; r++) {
            int row = arow + r * 32;
            float4 v = *reinterpret_cast<const float4*>(A + (size_t)(m0 + row) * K + k0 + acol);
            As[row][acol]     = f2tf(v.x);
            As[row][acol + 1] = f2tf(v.y);
            As[row][acol + 2] = f2tf(v.z);
            As[row][acol + 3] = f2tf(v.w);
        }
        #pragma unroll
        for (int r = 0; r < 2; r++) {
            int row = arow + r * 32;
            float4 v = *reinterpret_cast<const float4*>(W + (size_t)(n0 + row) * K + k0 + acol);
            Bs[row][acol]     = f2tf(v.x);
            Bs[row][acol + 1] = f2tf(v.y);
            Bs[row][acol + 2] = f2tf(v.z);
            Bs[row][acol + 3] = f2tf(v.w);
        }
        __syncthreads();

        #pragma unroll
        for (int kk = 0; kk < 32; kk += 8) {
            uint32_t af[2][4], bf[4][2];
            #pragma unroll
            for (int mf = 0; mf < 2; mf++) {
                int r0 = mb + mf * 16 + g4;
                af[mf][0] = As[r0][kk + tig];
                af[mf][1] = As[r0 + 8][kk + tig];
                af[mf][2] = As[r0][kk + tig + 4];
                af[mf][3] = As[r0 + 8][kk + tig + 4];
            }
            #pragma unroll
            for (int nf = 0; nf < 4; nf++) {
                int c0 = nb + nf * 8 + g4;
                bf[nf][0] = Bs[c0][kk + tig];
                bf[nf][1] = Bs[c0][kk + tig + 4];
            }
            #pragma unroll
            for (int mf = 0; mf < 2; mf++)
                #pragma unroll
                for (int nf = 0; nf < 4; nf++)
                    mma8(acc[mf][nf], af[mf], bf[nf]);
        }
        __syncthreads();
    }

    #pragma unroll
    for (int mf = 0; mf < 2; mf++) {
        #pragma unroll
        for (int nf = 0; nf < 4; nf++) {
            int col = n0 + nb + nf * 8 + tig * 2;
            float b0 = bias[col], b1 = bias[col + 1];
            int r0 = m0 + mb + mf * 16 + g4;
            g_gi[(size_t)r0 * G3H + col]           = acc[mf][nf][0] + b0;
            g_gi[(size_t)r0 * G3H + col + 1]       = acc[mf][nf][1] + b1;
            g_gi[(size_t)(r0 + 8) * G3H + col]     = acc[mf][nf][2] + b0;
            g_gi[(size_t)(r0 + 8) * G3H + col + 1] = acc[mf][nf][3] + b1;
        }
    }
}

// ---------------------------------------------------------------------------
// Persistent scan: all 256 GRU timesteps of one layer in ONE kernel.
// Grid = 128 CTAs (2 batch tiles x 64 col groups), 256 threads.
// h state lives in REGISTERS (thread->element map is time-invariant);
// a TF32-bits copy round-trips global for the K-dim reads, staged via
// double-buffered cp.async. W slice resident in smem all layer.
// ---------------------------------------------------------------------------
__global__ __launch_bounds__(256, 1) void gru_scan(
    const float* __restrict__ Whh,     // (3H, H) this layer
    const float* __restrict__ bhh,     // (3H)
    const int*   __restrict__ lens,
    const float* __restrict__ h0,      // initial hidden for this layer (B,H)
    float* __restrict__ y_last,        // d_out ys base if last layer, else null
    float* __restrict__ h_final)       // d_out h slice for this layer
{
    extern __shared__ uint32_t sm[];
    uint32_t* Ws = sm;                        // 48 x WS_STRIDE
    uint32_t* Ab = sm + 48 * WS_STRIDE;       // 2 x BUF_WORDS

    int cta = blockIdx.x;
    int bt = cta & 1;            // batch tile 0/1
    int cg = cta >> 1;           // col group 0..63
    int tid = threadIdx.x;
    int warp = tid >> 5, lane = tid & 31;
    int g4 = lane >> 2, tig = lane & 3;
    int wrow = warp & 3, wcol = warp >> 2;

    uint32_t ab_u32;
    {
        uint64_t p = __cvta_generic_to_shared(Ab);
        ab_u32 = (uint32_t)p;
    }

    // Load W slice into smem once (TF32)
    for (int i = tid; i < 48 * 256; i += 256) {
        int r = i >> 8;              // 0..47
        int c = (i & 255) << 2;      // 0..1020
        int q = r >> 4, rl = r & 15;
        float4 v = *reinterpret_cast<const float4*>(
            Whh + (size_t)(q * H_ + cg * CT + rl) * H_ + c);
        uint32_t* dst = Ws + r * WS_STRIDE + c;
        dst[0] = f2tf(v.x); dst[1] = f2tf(v.y); dst[2] = f2tf(v.z); dst[3] = f2tf(v.w);
    }

    // Per-thread constants + register-resident h (2 rows x 2 cols)
    int m0 = bt * RT + wrow * 16 + g4;          // rows m0, m0+8
    int jbase = cg * CT + wcol * 8 + tig * 2;   // col pair base (per gate)
    float bj[3][2];
    #pragma unroll
    for (int q = 0; q < 3; q++) {
        bj[q][0] = bhh[q * H_ + jbase];
        bj[q][1] = bhh[q * H_ + jbase + 1];
    }
    int len0 = lens[m0];
    int len1 = lens[m0 + 8];

    float hreg[2][2];
    #pragma unroll
    for (int ri = 0; ri < 2; ri++) {
        int m = m0 + ri * 8;
        hreg[ri][0] = h0[(size_t)m * H_ + jbase];
        hreg[ri][1] = h0[(size_t)m * H_ + jbase + 1];
        g_htf[0][(size_t)m * H_ + jbase]     = f2tf(hreg[ri][0]);
        g_htf[0][(size_t)m * H_ + jbase + 1] = f2tf(hreg[ri][1]);
    }

    // init grid barrier (phase 1)
    unsigned phase = 1;
    __syncthreads();
    if (tid == 0) {
        __threadfence();
        atomicAdd(&g_bar, 1u);
        unsigned v;
        do { asm volatile("ld.global.acquire.gpu.u32 %0, [%1];" : "=r"(v) : "l"(&g_bar) : "memory"); }
        while (v < 128u * phase);
    }
    __syncthreads();

    int srow = tid >> 4;                 // staging row base (0..15), +16*it
    int scol = (tid & 15) << 2;          // staging col (words)

    for (int t = 0; t < T_; t++) {
        const uint32_t* hin = g_htf[t & 1];
        uint32_t* hout = g_htf[(t & 1) ^ 1];

        // prefetch chunk 0
        {
            const uint32_t* src = hin + (size_t)(bt * RT) * H_;
            #pragma unroll
            for (int it = 0; it < 4; it++) {
                int row = srow + it * 16;
                cp16(ab_u32 + (uint32_t)(row * AS_STRIDE + scol) * 4,
                     src + (size_t)row * H_ + scol);
            }
            asm volatile("cp.async.commit_group;\n" ::: "memory");
        }

        // prefetch gi values for this step (hide DRAM latency behind GEMM)
        float gir[2][3][2];
        {
            const float* gi_t = g_gi + (size_t)t * B_ * G3H;
            #pragma unroll
            for (int ri = 0; ri < 2; ri++) {
                const float* gi = gi_t + (size_t)(m0 + ri * 8) * G3H;
                #pragma unroll
                for (int q = 0; q < 3; q++) {
                    gir[ri][q][0] = gi[q * H_ + jbase];
                    gir[ri][q][1] = gi[q * H_ + jbase + 1];
                }
            }
        }

        float acc[3][4];
        #pragma unroll
        for (int q = 0; q < 3; q++)
            #pragma unroll
            for (int i = 0; i < 4; i++) acc[q][i] = 0.f;

        for (int c = 0; c < 16; c++) {
            asm volatile("cp.async.wait_group 0;\n" ::: "memory");
            __syncthreads();
            if (c + 1 < 16) {
                int k0n = (c + 1) * 64;
                uint32_t dstb = ab_u32 + (uint32_t)(((c + 1) & 1) * BUF_WORDS) * 4;
                const uint32_t* src = hin + (size_t)(bt * RT) * H_ + k0n;
                #pragma unroll
                for (int it = 0; it < 4; it++) {
                    int row = srow + it * 16;
                    cp16(dstb + (uint32_t)(row * AS_STRIDE + scol) * 4,
                         src + (size_t)row * H_ + scol);
                }
                asm volatile("cp.async.commit_group;\n" ::: "memory");
            }

            const uint32_t* As = Ab + (c & 1) * BUF_WORDS;
            int k0 = c * 64;
            #pragma unroll
            for (int kk = 0; kk < 64; kk += 8) {
                uint32_t af[4];
                int r0 = (wrow * 16 + g4) * AS_STRIDE;
                af[0] = As[r0 + kk + tig];
                af[1] = As[r0 + 8 * AS_STRIDE + kk + tig];
                af[2] = As[r0 + kk + tig + 4];
                af[3] = As[r0 + 8 * AS_STRIDE + kk + tig + 4];
                #pragma unroll
                for (int q = 0; q < 3; q++) {
                    uint32_t bf[2];
                    int wr = (q * 16 + wcol * 8 + g4) * WS_STRIDE + k0 + kk;
                    bf[0] = Ws[wr + tig];
                    bf[1] = Ws[wr + tig + 4];
                    mma8(acc[q], af, bf);
                }
            }
        }

        // Fused gate epilogue (all state in registers)
        float* yrow = y_last ? (y_last + (size_t)t * B_ * H_)
                             : (g_ys + (size_t)t * B_ * H_);
        #pragma unroll
        for (int ri = 0; ri < 2; ri++) {
            int m = m0 + ri * 8;
            bool msk = t < (ri ? len1 : len0);
            #pragma unroll
            for (int ci = 0; ci < 2; ci++) {
                int j = jbase + ci;
                int ai = ri * 2 + ci;
                float ghr = acc[0][ai] + bj[0][ci];
                float ghz = acc[1][ai] + bj[1][ci];
                float ghn = acc[2][ai] + bj[2][ci];
                float rg = 1.f / (1.f + __expf(-(gir[ri][0][ci] + ghr)));
                float zg = 1.f / (1.f + __expf(-(gir[ri][1][ci] + ghz)));
                float ng = tanhf(gir[ri][2][ci] + rg * ghn);
                float hnew = (1.f - zg) * ng + zg * hreg[ri][ci];
                float hv = msk ? hnew : hreg[ri][ci];
                hreg[ri][ci] = hv;
                hout[(size_t)m * H_ + j] = f2tf(hv);
                yrow[(size_t)m * H_ + j] = msk ? hnew : 0.f;
                if (t == T_ - 1) h_final[(size_t)m * H_ + j] = hv;
            }
        }

        // Grid barrier
        phase++;
        __syncthreads();
        if (tid == 0) {
            __threadfence();
            atomicAdd(&g_bar, 1u);
            unsigned target = 128u * phase;
            unsigned v;
            do { asm volatile("ld.global.acquire.gpu.u32 %0, [%1];" : "=r"(v) : "l"(&g_bar) : "memory"); }
            while (v < target);
        }
        __syncthreads();
    }

    // reset barrier counter for next scan / next replay (last CTA to ack)
    if (tid == 0) {
        unsigned a = atomicAdd(&g_ack, 1u);
        if (a == 127u) {
            g_bar = 0u;
            g_ack = 0u;
            __threadfence();
        }
    }
}

extern "C" void kernel_launch(void* const* d_in, const int* in_sizes, int n_in,
                              void* d_out, int out_size) {
    const float* x          = (const float*)d_in[0];
    const float* hidden     = (const float*)d_in[1];
    const float* w_ih0      = (const float*)d_in[2];
    const float* w_ih_rest  = (const float*)d_in[3];
    const float* w_hh       = (const float*)d_in[4];
    const float* b_ih       = (const float*)d_in[5];
    const float* b_hh       = (const float*)d_in[6];
    const int*   lens       = (const int*)d_in[n_in - 1];  // input_lengths is last

    float* out_ys = (float*)d_out;                       // (T, B, H)
    float* out_h  = out_ys + (size_t)T_ * B_ * H_;       // (L, B, H)

    cudaFuncSetAttribute(gru_scan, cudaFuncAttributeMaxDynamicSharedMemorySize,
                         SCAN_SMEM_BYTES);

    for (int l = 0; l < L_; l++) {
        int K = (l == 0) ? I_ : H_;
        const float* wih = (l == 0) ? w_ih0 : (w_ih_rest + (size_t)(l - 1) * G3H * H_);
        dim3 grid(G3H / 64, TB / 128);
        gi_gemm<<<grid, 256>>>((l == 0) ? x : nullptr, wih, b_ih + (size_t)l * G3H, K);

        gru_scan<<<128, 256, SCAN_SMEM_BYTES>>>(
            w_hh + (size_t)l * G3H * H_,
            b_hh + (size_t)l * G3H,
            lens,
            hidden + (size_t)l * B_ * H_,
            (l == L_ - 1) ? out_ys : nullptr,
            out_h + (size_t)l * B_ * H_);
    }
}

// round 4
// speedup vs baseline: 1.6470x; 1.1344x over previous
#include <cuda_runtime.h>
#include <cstdint>

#define T_  256
#define B_  128
#define I_  512
#define H_  1024
#define L_  4
#define G3H 3072
#define TB  (T_ * B_)

// scan tiling
#define RT 64            // batch rows per CTA
#define CT 16            // cols per gate per CTA (48 W rows total)
// fragment-packed h: row-block (16 rows) x 1024 k = 16384 words
#define RBW 16384
// per-chunk staging: 4 row-blocks x 8 ko x 128 words = 4096 words
#define CHUNK_WORDS 4096
#define WS_WORDS (48 * 1024)          // 49152 words, fragment-packed W
#define SCAN_SMEM_WORDS (WS_WORDS + 2 * CHUNK_WORDS)
#define SCAN_SMEM_BYTES (SCAN_SMEM_WORDS * 4)   // 229376 <= 232448

// Scratch
__device__ float    g_gi[(size_t)TB * G3H];   // per-layer input projections
__device__ float    g_ys[(size_t)TB * H_];    // inter-layer activations
__device__ uint32_t g_htf[2][B_ * H_];        // ping-pong hidden, TF32 bits, FRAGMENT-PACKED
__device__ unsigned g_bar;                    // grid barrier counter
__device__ unsigned g_ack;                    // end-of-scan reset ack

__device__ __forceinline__ uint32_t f2tf(float x) {
    uint32_t r;
    asm("cvt.rna.tf32.f32 %0, %1;\n" : "=r"(r) : "f"(x));
    return r;
}

__device__ __forceinline__ void mma8(float* c, const uint32_t* a, const uint32_t* b) {
    asm volatile(
        "mma.sync.aligned.m16n8k8.row.col.f32.tf32.tf32.f32 "
        "{%0,%1,%2,%3}, {%4,%5,%6,%7}, {%8,%9}, {%0,%1,%2,%3};\n"
        : "+f"(c[0]), "+f"(c[1]), "+f"(c[2]), "+f"(c[3])
        : "r"(a[0]), "r"(a[1]), "r"(a[2]), "r"(a[3]), "r"(b[0]), "r"(b[1]));
}

__device__ __forceinline__ void cp16cg(uint32_t dst_smem, const void* src) {
    asm volatile("cp.async.cg.shared.global [%0], [%1], 16;\n"
                 :: "r"(dst_smem), "l"(src));
}

// packed address of h element (m, k)
__device__ __forceinline__ int hpack(int m, int k) {
    return (m >> 4) * RBW + (k >> 3) * 128 +
           ((m & 7) * 4 + (k & 3)) * 4 + ((m >> 3) & 1) + 2 * ((k >> 2) & 1);
}

// ---------------------------------------------------------------------------
// gi = A @ W^T + bias      (unchanged from round 3)
// ---------------------------------------------------------------------------
__global__ __launch_bounds__(256) void gi_gemm(
    const float* __restrict__ A_ext,
    const float* __restrict__ W,
    const float* __restrict__ bias,
    int K)
{
    __shared__ uint32_t As[128][36];
    __shared__ uint32_t Bs[64][36];

    const float* A = A_ext ? A_ext : g_ys;

    int n0 = blockIdx.x * 64;
    int m0 = blockIdx.y * 128;
    int tid = threadIdx.x;
    int warp = tid >> 5, lane = tid & 31;
    int g4 = lane >> 2, tig = lane & 3;
    int wm = warp & 3, wn = warp >> 2;
    int mb = wm * 32, nb = wn * 32;

    float acc[2][4][4];
    #pragma unroll
    for (int i = 0; i < 2; i++)
        #pragma unroll
        for (int j = 0; j < 4; j++)
            #pragma unroll
            for (int k = 0; k < 4; k++) acc[i][j][k] = 0.f;

    int arow = tid >> 3;
    int acol = (tid & 7) * 4;

    for (int k0 = 0; k0 < K; k0 += 32) {
        #pragma unroll
        for (int r = 0; r < 4; r++) {
            int row = arow + r * 32;
            float4 v = *reinterpret_cast<const float4*>(A + (size_t)(m0 + row) * K + k0 + acol);
            As[row][acol]     = f2tf(v.x);
            As[row][acol + 1] = f2tf(v.y);
            As[row][acol + 2] = f2tf(v.z);
            As[row][acol + 3] = f2tf(v.w);
        }
        #pragma unroll
        for (int r = 0; r < 2; r++) {
            int row = arow + r * 32;
            float4 v = *reinterpret_cast<const float4*>(W + (size_t)(n0 + row) * K + k0 + acol);
            Bs[row][acol]     = f2tf(v.x);
            Bs[row][acol + 1] = f2tf(v.y);
            Bs[row][acol + 2] = f2tf(v.z);
            Bs[row][acol + 3] = f2tf(v.w);
        }
        __syncthreads();

        #pragma unroll
        for (int kk = 0; kk < 32; kk += 8) {
            uint32_t af[2][4], bf[4][2];
            #pragma unroll
            for (int mf = 0; mf < 2; mf++) {
                int r0 = mb + mf * 16 + g4;
                af[mf][0] = As[r0][kk + tig];
                af[mf][1] = As[r0 + 8][kk + tig];
                af[mf][2] = As[r0][kk + tig + 4];
                af[mf][3] = As[r0 + 8][kk + tig + 4];
            }
            #pragma unroll
            for (int nf = 0; nf < 4; nf++) {
                int c0 = nb + nf * 8 + g4;
                bf[nf][0] = Bs[c0][kk + tig];
                bf[nf][1] = Bs[c0][kk + tig + 4];
            }
            #pragma unroll
            for (int mf = 0; mf < 2; mf++)
                #pragma unroll
                for (int nf = 0; nf < 4; nf++)
                    mma8(acc[mf][nf], af[mf], bf[nf]);
        }
        __syncthreads();
    }

    #pragma unroll
    for (int mf = 0; mf < 2; mf++) {
        #pragma unroll
        for (int nf = 0; nf < 4; nf++) {
            int col = n0 + nb + nf * 8 + tig * 2;
            float b0 = bias[col], b1 = bias[col + 1];
            int r0 = m0 + mb + mf * 16 + g4;
            g_gi[(size_t)r0 * G3H + col]           = acc[mf][nf][0] + b0;
            g_gi[(size_t)r0 * G3H + col + 1]       = acc[mf][nf][1] + b1;
            g_gi[(size_t)(r0 + 8) * G3H + col]     = acc[mf][nf][2] + b0;
            g_gi[(size_t)(r0 + 8) * G3H + col + 1] = acc[mf][nf][3] + b1;
        }
    }
}

// ---------------------------------------------------------------------------
// Persistent scan, fragment-packed layouts.
// Grid = 128 CTAs (2 batch tiles x 64 col groups), 256 threads (8 warps:
// wrow 0..3 = 16-row blocks, wcol 0..1 = 8-col groups per gate).
// A-fragments: 1x LDS.128 each; B-fragments: 1x LDS.64 each.
// ---------------------------------------------------------------------------
__global__ __launch_bounds__(256, 1) void gru_scan(
    const float* __restrict__ Whh,
    const float* __restrict__ bhh,
    const int*   __restrict__ lens,
    const float* __restrict__ h0,
    float* __restrict__ y_last,
    float* __restrict__ h_final)
{
    extern __shared__ uint32_t sm[];
    uint32_t* Ws = sm;                     // WS_WORDS, fragment-packed
    uint32_t* Ab = sm + WS_WORDS;          // 2 x CHUNK_WORDS

    int cta = blockIdx.x;
    int bt = cta & 1;
    int cg = cta >> 1;
    int tid = threadIdx.x;
    int lane = tid & 31;
    int warp = tid >> 5;
    int g4 = lane >> 2, tig = lane & 3;
    int wrow = warp & 3, wcol = warp >> 2;

    uint32_t ab_u32 = (uint32_t)__cvta_generic_to_shared(Ab);

    // Pack W slice into smem fragment order:
    // Ws[((q*2+wc)*128 + ko)*64 + l*2 + w] = W[q*H + cg*16 + wc*8 + (l>>2)][ko*8 + (l&3) + 4*w]
    for (int i = tid; i < 48 * 256; i += 256) {
        int r = i >> 8;                  // packed W row 0..47
        int c4 = i & 255;                // float4 index along K
        int q = r >> 4;
        int rl = r & 15;
        int wc = rl >> 3, g4r = rl & 7;
        float4 v = *reinterpret_cast<const float4*>(
            Whh + (size_t)(q * H_ + cg * CT + rl) * H_ + c4 * 4);
        int ko = c4 >> 1;
        int hi = c4 & 1;                 // (k>>2)&1
        uint32_t* base = Ws + ((size_t)(q * 2 + wc) * 128 + ko) * 64 + g4r * 8 + hi;
        // elements e=0..3: lane = g4r*4+e, word = hi
        base[0] = f2tf(v.x);             // e=0: +0*2
        base[2] = f2tf(v.y);             // e=1
        base[4] = f2tf(v.z);
        base[6] = f2tf(v.w);
    }

    // Per-thread constants + register-resident h
    int m0 = bt * RT + wrow * 16 + g4;
    int jbase = cg * CT + wcol * 8 + tig * 2;
    float bj[3][2];
    #pragma unroll
    for (int q = 0; q < 3; q++) {
        bj[q][0] = bhh[q * H_ + jbase];
        bj[q][1] = bhh[q * H_ + jbase + 1];
    }
    int len0 = lens[m0];
    int len1 = lens[m0 + 8];

    float hreg[2][2];
    #pragma unroll
    for (int ri = 0; ri < 2; ri++) {
        int m = m0 + ri * 8;
        #pragma unroll
        for (int ci = 0; ci < 2; ci++) {
            hreg[ri][ci] = h0[(size_t)m * H_ + jbase + ci];
            g_htf[0][hpack(m, jbase + ci)] = f2tf(hreg[ri][ci]);
        }
    }

    // init grid barrier (phase 1)
    unsigned phase = 1;
    __syncthreads();
    if (tid == 0) {
        __threadfence();
        atomicAdd(&g_bar, 1u);
        unsigned v;
        do { asm volatile("ld.global.acquire.gpu.u32 %0, [%1];" : "=r"(v) : "l"(&g_bar) : "memory"); }
        while (v < 128u * phase);
    }
    __syncthreads();

    for (int t = 0; t < T_; t++) {
        const uint32_t* hin = g_htf[t & 1];
        uint32_t* hout = g_htf[(t & 1) ^ 1];

        // prefetch chunk 0 (contiguous fragment-packed copies)
        {
            #pragma unroll
            for (int it = 0; it < 4; it++) {
                cp16cg(ab_u32 + (uint32_t)(it * 1024 + tid * 4) * 4,
                       hin + (size_t)(bt * 4 + it) * RBW + tid * 4);
            }
            asm volatile("cp.async.commit_group;\n" ::: "memory");
        }

        // prefetch gi for this step
        float gir[2][3][2];
        {
            const float* gi_t = g_gi + (size_t)t * B_ * G3H;
            #pragma unroll
            for (int ri = 0; ri < 2; ri++) {
                const float* gi = gi_t + (size_t)(m0 + ri * 8) * G3H;
                #pragma unroll
                for (int q = 0; q < 3; q++) {
                    gir[ri][q][0] = gi[q * H_ + jbase];
                    gir[ri][q][1] = gi[q * H_ + jbase + 1];
                }
            }
        }

        float acc[3][4];
        #pragma unroll
        for (int q = 0; q < 3; q++)
            #pragma unroll
            for (int i = 0; i < 4; i++) acc[q][i] = 0.f;

        for (int c = 0; c < 16; c++) {
            asm volatile("cp.async.wait_group 0;\n" ::: "memory");
            __syncthreads();
            if (c + 1 < 16) {
                uint32_t dstb = ab_u32 + (uint32_t)(((c + 1) & 1) * CHUNK_WORDS) * 4;
                #pragma unroll
                for (int it = 0; it < 4; it++) {
                    cp16cg(dstb + (uint32_t)(it * 1024 + tid * 4) * 4,
                           hin + (size_t)(bt * 4 + it) * RBW + (c + 1) * 1024 + it * 0 + tid * 4);
                }
                asm volatile("cp.async.commit_group;\n" ::: "memory");
            }

            const uint32_t* As = Ab + (c & 1) * CHUNK_WORDS + wrow * 1024 + lane * 4;
            #pragma unroll
            for (int kk8 = 0; kk8 < 8; kk8++) {
                uint4 af = *reinterpret_cast<const uint4*>(As + kk8 * 128);
                #pragma unroll
                for (int q = 0; q < 3; q++) {
                    uint2 bf = *reinterpret_cast<const uint2*>(
                        Ws + ((size_t)(q * 2 + wcol) * 128 + c * 8 + kk8) * 64 + lane * 2);
                    mma8(acc[q], reinterpret_cast<const uint32_t*>(&af),
                                 reinterpret_cast<const uint32_t*>(&bf));
                }
            }
        }

        // Gate epilogue: compute + write packed h
        float ynew[2][2];
        #pragma unroll
        for (int ri = 0; ri < 2; ri++) {
            int m = m0 + ri * 8;
            bool msk = t < (ri ? len1 : len0);
            #pragma unroll
            for (int ci = 0; ci < 2; ci++) {
                int ai = ri * 2 + ci;
                float ghr = acc[0][ai] + bj[0][ci];
                float ghz = acc[1][ai] + bj[1][ci];
                float ghn = acc[2][ai] + bj[2][ci];
                float rg = 1.f / (1.f + __expf(-(gir[ri][0][ci] + ghr)));
                float zg = 1.f / (1.f + __expf(-(gir[ri][1][ci] + ghz)));
                float ng = tanhf(gir[ri][2][ci] + rg * ghn);
                float hnew = (1.f - zg) * ng + zg * hreg[ri][ci];
                float hv = msk ? hnew : hreg[ri][ci];
                hreg[ri][ci] = hv;
                ynew[ri][ci] = msk ? hnew : 0.f;
                hout[hpack(m, jbase + ci)] = f2tf(hv);
            }
        }

        // barrier arrive (h writes visible), overlap y/h_final stores with wait
        phase++;
        __syncthreads();
        if (tid == 0) {
            __threadfence();
            atomicAdd(&g_bar, 1u);
        }

        float* yrow = y_last ? (y_last + (size_t)t * B_ * H_)
                             : (g_ys + (size_t)t * B_ * H_);
        #pragma unroll
        for (int ri = 0; ri < 2; ri++) {
            int m = m0 + ri * 8;
            yrow[(size_t)m * H_ + jbase]     = ynew[ri][0];
            yrow[(size_t)m * H_ + jbase + 1] = ynew[ri][1];
            if (t == T_ - 1) {
                h_final[(size_t)m * H_ + jbase]     = hreg[ri][0];
                h_final[(size_t)m * H_ + jbase + 1] = hreg[ri][1];
            }
        }

        if (tid == 0) {
            unsigned target = 128u * phase;
            unsigned v;
            do { asm volatile("ld.global.acquire.gpu.u32 %0, [%1];" : "=r"(v) : "l"(&g_bar) : "memory"); }
            while (v < target);
        }
        __syncthreads();
    }

    // reset barrier for next scan / replay
    if (tid == 0) {
        unsigned a = atomicAdd(&g_ack, 1u);
        if (a == 127u) {
            g_bar = 0u;
            g_ack = 0u;
            __threadfence();
        }
    }
}

extern "C" void kernel_launch(void* const* d_in, const int* in_sizes, int n_in,
                              void* d_out, int out_size) {
    const float* x          = (const float*)d_in[0];
    const float* hidden     = (const float*)d_in[1];
    const float* w_ih0      = (const float*)d_in[2];
    const float* w_ih_rest  = (const float*)d_in[3];
    const float* w_hh       = (const float*)d_in[4];
    const float* b_ih       = (const float*)d_in[5];
    const float* b_hh       = (const float*)d_in[6];
    const int*   lens       = (const int*)d_in[n_in - 1];

    float* out_ys = (float*)d_out;
    float* out_h  = out_ys + (size_t)T_ * B_ * H_;

    cudaFuncSetAttribute(gru_scan, cudaFuncAttributeMaxDynamicSharedMemorySize,
                         SCAN_SMEM_BYTES);

    for (int l = 0; l < L_; l++) {
        int K = (l == 0) ? I_ : H_;
        const float* wih = (l == 0) ? w_ih0 : (w_ih_rest + (size_t)(l - 1) * G3H * H_);
        dim3 grid(G3H / 64, TB / 128);
        gi_gemm<<<grid, 256>>>((l == 0) ? x : nullptr, wih, b_ih + (size_t)l * G3H, K);

        gru_scan<<<128, 256, SCAN_SMEM_BYTES>>>(
            w_hh + (size_t)l * G3H * H_,
            b_hh + (size_t)l * G3H,
            lens,
            hidden + (size_t)l * B_ * H_,
            (l == L_ - 1) ? out_ys : nullptr,
            out_h + (size_t)l * B_ * H_);
    }
}